// round 3
// baseline (speedup 1.0000x reference)
#include <cuda_runtime.h>
#include <math.h>

namespace {
constexpr int B_   = 256;
constexpr int L_   = 256;
constexpr int C_   = 128;
constexpr int HID_ = 128;
constexpr int H_   = 4;
constexpr int D_   = 32;
constexpr int E_   = 4096;
constexpr int EG_  = E_ + C_;     // 4224 edges per graph incl. self loops
constexpr float NEG_SLOPE_ = 0.2f;

constexpr int HS = 130;           // row stride (floats) for node-feature smem buffers
constexpr int TS = 132;           // row stride (floats) for GEMM k-tiles

constexpr int SM_H   = 0;                 // h  : 128 x 130
constexpr int SM_XL  = 128 * HS;          // xl : 128 x 130
constexpr int SM_XR  = 2 * 128 * HS;      // xr : 128 x 130
constexpr int SM_LOG = 3 * 128 * HS;      // logits (4224 floats) / GEMM tiles
constexpr int SM_AS  = SM_LOG;            // 16 x 132
constexpr int SM_BS  = SM_LOG + 16 * TS;  // 16 x 132
constexpr int SM_FLOATS = SM_LOG + 2 * 16 * TS;   // 54144 floats

constexpr int SMEM_BYTES = SM_FLOATS * 4  // float region
                         + 130 * 4        // rowptr
                         + EG_ * 2        // srcs  (u16)
                         + EG_            // dstof (u8)
                         + 64;            // pad
}

__device__ int            g_rowptr[C_ + 1];
__device__ unsigned short g_srcs[EG_];
__device__ unsigned char  g_dstof[EG_];

// ---------------------------------------------------------------------------
// Preprocessing: detect int32 vs int64 edge_index, build dst-sorted CSR.
// Runs every launch (graph-replay safe), single CTA, trivially cheap.
// ---------------------------------------------------------------------------
__global__ void prep_kernel(const int* __restrict__ ei) {
    __shared__ int deg[C_];
    __shared__ int cur[C_];
    __shared__ int s_is64;
    int tid = threadIdx.x;
    if (tid == 0) s_is64 = 1;
    __syncthreads();
    // If data is int64 (little-endian, values in [0,128)), every odd 32-bit
    // word of the first 8192 words is 0. For int32 data those words are random
    // node indices -> someone flips the flag.
    int bad = 0;
    for (int i = tid; i < E_; i += blockDim.x)
        if (ei[2 * i + 1] != 0) bad = 1;
    if (bad) s_is64 = 0;
    __syncthreads();
    const int is64 = s_is64;

    for (int i = tid; i < C_; i += blockDim.x) deg[i] = 1;  // self loop
    __syncthreads();
    for (int e = tid; e < E_; e += blockDim.x) {
        int dst = is64 ? ei[2 * E_ + 2 * e] : ei[E_ + e];
        atomicAdd(&deg[dst], 1);
    }
    __syncthreads();
    if (tid == 0) {
        int acc = 0;
        for (int n = 0; n < C_; n++) { g_rowptr[n] = acc; cur[n] = acc; acc += deg[n]; }
        g_rowptr[C_] = acc;  // == EG_
    }
    __syncthreads();
    for (int e = tid; e < E_; e += blockDim.x) {
        int src = is64 ? ei[2 * e] : ei[e];
        int dst = is64 ? ei[2 * E_ + 2 * e] : ei[E_ + e];
        int p = atomicAdd(&cur[dst], 1);
        g_srcs[p]  = (unsigned short)src;
        g_dstof[p] = (unsigned char)dst;
    }
    __syncthreads();
    for (int n = tid; n < C_; n += blockDim.x) {
        int p = atomicAdd(&cur[n], 1);
        g_srcs[p]  = (unsigned short)n;
        g_dstof[p] = (unsigned char)n;
    }
}

// ---------------------------------------------------------------------------
// Warp reductions
// ---------------------------------------------------------------------------
__device__ __forceinline__ float warpSum(float v) {
    #pragma unroll
    for (int o = 16; o > 0; o >>= 1) v += __shfl_xor_sync(0xFFFFFFFFu, v, o);
    return v;
}
__device__ __forceinline__ float warpMax(float v) {
    #pragma unroll
    for (int o = 16; o > 0; o >>= 1) v = fmaxf(v, __shfl_xor_sync(0xFFFFFFFFu, v, o));
    return v;
}

// ---------------------------------------------------------------------------
// Main kernel: one CTA per batch. Entire pipeline per batch in shared memory.
// ---------------------------------------------------------------------------
__global__ __launch_bounds__(256) void gat_main_kernel(
    const float* __restrict__ x,
    const float* __restrict__ embW, const float* __restrict__ embB,
    const float* __restrict__ lW,   const float* __restrict__ lb,
    const float* __restrict__ rW,   const float* __restrict__ rb,
    const float* __restrict__ att,  const float* __restrict__ gbias,
    const float* __restrict__ lng,  const float* __restrict__ lnb,
    const float* __restrict__ pW,   const float* __restrict__ pb,
    float* __restrict__ out)
{
    extern __shared__ float sm[];
    int*            s_rowptr = (int*)(sm + SM_FLOATS);
    unsigned short* s_srcs   = (unsigned short*)(s_rowptr + 130);
    unsigned char*  s_dstof  = (unsigned char*)(s_srcs + EG_);

    const int b    = blockIdx.x;
    const int tid  = threadIdx.x;
    const int tx   = tid & 15;
    const int ty   = tid >> 4;
    const int lane = tid & 31;
    const int warp = tid >> 5;

    float* attn_out = out + (size_t)B_ * L_ * C_;
    float* myattn   = attn_out + (size_t)b * C_ * C_;

    // --- load CSR into smem, zero this batch's attn-map region ---
    for (int i = tid; i <= C_; i += 256) s_rowptr[i] = g_rowptr[i];
    for (int i = tid; i < EG_; i += 256) { s_srcs[i] = g_srcs[i]; s_dstof[i] = g_dstof[i]; }
    for (int i = tid; i < C_ * C_; i += 256) myattn[i] = 0.0f;
    __syncthreads();

    float acc[8][8];

    // ================= Embedding GEMM: h = X_b^T(128x256) @ embW(256x128) + b =========
    #pragma unroll
    for (int ii = 0; ii < 8; ii++)
        #pragma unroll
        for (int jj = 0; jj < 8; jj++) acc[ii][jj] = 0.0f;

    const float* xb = x + (size_t)b * L_ * C_;
    for (int k0 = 0; k0 < L_; k0 += 16) {
        #pragma unroll
        for (int r = 0; r < 8; r++) {
            int i = tid + 256 * r;
            int kk = i >> 7, c = i & 127;
            sm[SM_AS + kk * TS + c] = xb[(k0 + kk) * C_ + c];
            sm[SM_BS + kk * TS + c] = embW[(k0 + kk) * HID_ + c];
        }
        __syncthreads();
        #pragma unroll
        for (int kk = 0; kk < 16; kk++) {
            float a[8], bb[8];
            #pragma unroll
            for (int ii = 0; ii < 8; ii++) a[ii]  = sm[SM_AS + kk * TS + ty + 16 * ii];
            #pragma unroll
            for (int jj = 0; jj < 8; jj++) bb[jj] = sm[SM_BS + kk * TS + tx + 16 * jj];
            #pragma unroll
            for (int ii = 0; ii < 8; ii++)
                #pragma unroll
                for (int jj = 0; jj < 8; jj++) acc[ii][jj] += a[ii] * bb[jj];
        }
        __syncthreads();
    }
    #pragma unroll
    for (int jj = 0; jj < 8; jj++) {
        float bi = embB[tx + 16 * jj];
        #pragma unroll
        for (int ii = 0; ii < 8; ii++)
            sm[SM_H + (ty + 16 * ii) * HS + tx + 16 * jj] = acc[ii][jj] + bi;
    }
    __syncthreads();

    // ================= Layers =========================================================
    for (int li = 0; li < 2; li++) {
        // --- xl = h @ Wl + bl ; xr = h @ Wr + br (A read from smem h) ---
        for (int which = 0; which < 2; which++) {
            const float* W  = (which == 0 ? lW : rW) + (size_t)li * HID_ * HID_;
            const float* Bv = (which == 0 ? lb : rb) + li * HID_;
            const int dsto  = (which == 0) ? SM_XL : SM_XR;
            #pragma unroll
            for (int ii = 0; ii < 8; ii++)
                #pragma unroll
                for (int jj = 0; jj < 8; jj++) acc[ii][jj] = 0.0f;
            for (int k0 = 0; k0 < HID_; k0 += 16) {
                #pragma unroll
                for (int r = 0; r < 8; r++) {
                    int i = tid + 256 * r;
                    int kk = i >> 7, j = i & 127;
                    sm[SM_BS + kk * TS + j] = W[(k0 + kk) * HID_ + j];
                }
                __syncthreads();
                #pragma unroll
                for (int kk = 0; kk < 16; kk++) {
                    float a[8], bb[8];
                    #pragma unroll
                    for (int ii = 0; ii < 8; ii++) a[ii]  = sm[SM_H + (ty + 16 * ii) * HS + k0 + kk];
                    #pragma unroll
                    for (int jj = 0; jj < 8; jj++) bb[jj] = sm[SM_BS + kk * TS + tx + 16 * jj];
                    #pragma unroll
                    for (int ii = 0; ii < 8; ii++)
                        #pragma unroll
                        for (int jj = 0; jj < 8; jj++) acc[ii][jj] += a[ii] * bb[jj];
                }
                __syncthreads();
            }
            #pragma unroll
            for (int jj = 0; jj < 8; jj++) {
                float bi = Bv[tx + 16 * jj];
                #pragma unroll
                for (int ii = 0; ii < 8; ii++)
                    sm[dsto + (ty + 16 * ii) * HS + tx + 16 * jj] = acc[ii][jj] + bi;
            }
            __syncthreads();
        }

        // --- edge phase, one head at a time; GAT output written into freed xr slice ---
        for (int hh = 0; hh < H_; hh++) {
            const float ad = att[(li * H_ + hh) * D_ + lane];
            // logits: warp per edge, lane = d
            for (int e = warp; e < EG_; e += 8) {
                int s = s_srcs[e], d = s_dstof[e];
                float v = sm[SM_XL + s * HS + hh * D_ + lane]
                        + sm[SM_XR + d * HS + hh * D_ + lane];
                v = v > 0.0f ? v : NEG_SLOPE_ * v;
                v = warpSum(v * ad);
                if (lane == 0) sm[SM_LOG + e] = v;
            }
            __syncthreads();
            // softmax + aggregation: warp per dst node (exclusive row ownership)
            for (int n = warp; n < C_; n += 8) {
                int beg = s_rowptr[n], end = s_rowptr[n + 1];
                float m = -1e30f;
                for (int t = beg + lane; t < end; t += 32) m = fmaxf(m, sm[SM_LOG + t]);
                m = warpMax(m);
                float ssum = 0.0f;
                for (int t = beg + lane; t < end; t += 32) {
                    float p = __expf(sm[SM_LOG + t] - m);
                    sm[SM_LOG + t] = p;
                    ssum += p;
                }
                ssum = warpSum(ssum);
                float inv = 1.0f / (ssum + 1e-16f);
                __syncwarp();
                float av = 0.0f;
                for (int t = beg; t < end; t++) {
                    float al = sm[SM_LOG + t] * inv;
                    int s = s_srcs[t];
                    av += al * sm[SM_XL + s * HS + hh * D_ + lane];
                }
                sm[SM_XR + n * HS + hh * D_ + lane] = av;   // head slice hh of xr is dead now
                if (li == 1) {  // final-layer alpha -> attn map (mean over heads)
                    for (int t = beg + lane; t < end; t += 32)
                        atomicAdd(&myattn[n * C_ + s_srcs[t]], sm[SM_LOG + t] * inv * 0.25f);
                }
            }
            __syncthreads();
        }

        // --- bias + ELU + residual + LayerNorm -> h (warp per node) ---
        for (int n = warp; n < C_; n += 8) {
            float v[4];
            float ssum = 0.0f;
            #pragma unroll
            for (int q = 0; q < 4; q++) {
                int j = lane + 32 * q;
                float g = sm[SM_XR + n * HS + j] + gbias[li * HID_ + j];
                g = g > 0.0f ? g : expm1f(g);
                v[q] = sm[SM_H + n * HS + j] + g;
                ssum += v[q];
            }
            ssum = warpSum(ssum);
            float mu = ssum * (1.0f / 128.0f);
            float vs = 0.0f;
            #pragma unroll
            for (int q = 0; q < 4; q++) { float d = v[q] - mu; vs += d * d; }
            vs = warpSum(vs);
            float rstd = rsqrtf(vs * (1.0f / 128.0f) + 1e-5f);
            #pragma unroll
            for (int q = 0; q < 4; q++) {
                int j = lane + 32 * q;
                sm[SM_H + n * HS + j] = (v[q] - mu) * rstd * lng[li * HID_ + j] + lnb[li * HID_ + j];
            }
        }
        __syncthreads();
    }

    // ================= Projection: out[b,l,c] = h[c,:] . pW[:,l] + pb[l] ==============
    for (int half = 0; half < 2; half++) {
        #pragma unroll
        for (int ii = 0; ii < 8; ii++)
            #pragma unroll
            for (int jj = 0; jj < 8; jj++) acc[ii][jj] = 0.0f;
        for (int k0 = 0; k0 < HID_; k0 += 16) {
            #pragma unroll
            for (int r = 0; r < 8; r++) {
                int i = tid + 256 * r;
                int kk = i >> 7, ll = i & 127;
                sm[SM_BS + kk * TS + ll] = pW[(k0 + kk) * L_ + half * 128 + ll];
            }
            __syncthreads();
            #pragma unroll
            for (int kk = 0; kk < 16; kk++) {
                float a[8], bb[8];
                #pragma unroll
                for (int ii = 0; ii < 8; ii++) a[ii]  = sm[SM_H + (ty + 16 * ii) * HS + k0 + kk];
                #pragma unroll
                for (int jj = 0; jj < 8; jj++) bb[jj] = sm[SM_BS + kk * TS + tx + 16 * jj];
                #pragma unroll
                for (int ii = 0; ii < 8; ii++)
                    #pragma unroll
                    for (int jj = 0; jj < 8; jj++) acc[ii][jj] += a[ii] * bb[jj];
            }
            __syncthreads();
        }
        // stage into smem (xl buffer, free by now) as [l_local][c] for coalesced writes
        #pragma unroll
        for (int jj = 0; jj < 8; jj++) {
            float bi = pb[half * 128 + tx + 16 * jj];
            #pragma unroll
            for (int ii = 0; ii < 8; ii++)
                sm[SM_XL + (tx + 16 * jj) * HS + ty + 16 * ii] = acc[ii][jj] + bi;
        }
        __syncthreads();
        for (int idx = tid; idx < 128 * C_; idx += 256) {
            int ll = idx >> 7, c = idx & 127;
            out[(size_t)b * L_ * C_ + (half * 128 + ll) * C_ + c] = sm[SM_XL + ll * HS + c];
        }
        __syncthreads();
    }
}

// ---------------------------------------------------------------------------
extern "C" void kernel_launch(void* const* d_in, const int* in_sizes, int n_in,
                              void* d_out, int out_size)
{
    const float* x    = (const float*)d_in[0];
    const int*   ei   = (const int*)  d_in[1];   // int32 or int64 (auto-detected)
    const float* embW = (const float*)d_in[2];
    const float* embB = (const float*)d_in[3];
    const float* lW   = (const float*)d_in[4];
    const float* lb   = (const float*)d_in[5];
    const float* rW   = (const float*)d_in[6];
    const float* rb   = (const float*)d_in[7];
    const float* att  = (const float*)d_in[8];
    const float* gb   = (const float*)d_in[9];
    const float* lng  = (const float*)d_in[10];
    const float* lnb  = (const float*)d_in[11];
    const float* pW   = (const float*)d_in[12];
    const float* pb   = (const float*)d_in[13];

    cudaFuncSetAttribute(gat_main_kernel,
                         cudaFuncAttributeMaxDynamicSharedMemorySize, SMEM_BYTES);

    prep_kernel<<<1, 256>>>(ei);
    gat_main_kernel<<<B_, 256, SMEM_BYTES>>>(x, embW, embB, lW, lb, rW, rb,
                                             att, gb, lng, lnb, pW, pb,
                                             (float*)d_out);
}

// round 4
// speedup vs baseline: 1.5441x; 1.5441x over previous
#include <cuda_runtime.h>
#include <math.h>

namespace {
constexpr int B_   = 256;
constexpr int L_   = 256;
constexpr int C_   = 128;
constexpr int HID_ = 128;
constexpr int H_   = 4;
constexpr int D_   = 32;
constexpr int E_   = 4096;
constexpr int EG_  = E_ + C_;     // 4224 edges per graph incl. self loops

constexpr int THREADS = 512;

constexpr int HS = 129;           // row stride (floats) for node-feature smem buffers
constexpr int TS = 132;           // row stride (floats) for GEMM k-tiles

constexpr int SM_H   = 0;                 // h  : 128 x 129
constexpr int SM_XL  = 128 * HS;          // xl : 128 x 129
constexpr int SM_XR  = 2 * 128 * HS;      // xr : 128 x 129
constexpr int SM_LOG = 3 * 128 * HS;      // logits (4224 floats) / GEMM tiles (overlap)
constexpr int SM_AS  = SM_LOG;            // 16 x 132
constexpr int SM_BS  = SM_LOG + 16 * TS;  // 16 x 132
constexpr int SM_FLOATS = SM_LOG + 2 * 16 * TS;   // 53760 floats

constexpr int SMEM_BYTES = SM_FLOATS * 4  // float region
                         + 132 * 4        // rowptr
                         + 256 * 4        // att cache (2 layers x 4 heads x 32)
                         + EG_ * 2        // srcs  (u16)
                         + EG_            // dstof (u8)
                         + 64;            // pad
}

__device__ int            g_rowptr[C_ + 1];
__device__ unsigned short g_srcs[EG_];
__device__ unsigned char  g_dstof[EG_];

// ---------------------------------------------------------------------------
// Preprocessing: detect int32 vs int64 edge_index, build dst-sorted CSR.
// ---------------------------------------------------------------------------
__global__ void prep_kernel(const int* __restrict__ ei) {
    __shared__ int deg[C_];
    __shared__ int cur[C_];
    __shared__ int s_is64;
    int tid = threadIdx.x;
    if (tid == 0) s_is64 = 1;
    __syncthreads();
    int bad = 0;
    for (int i = tid; i < E_; i += blockDim.x)
        if (ei[2 * i + 1] != 0) bad = 1;
    if (bad) s_is64 = 0;
    __syncthreads();
    const int is64 = s_is64;

    for (int i = tid; i < C_; i += blockDim.x) deg[i] = 1;  // self loop
    __syncthreads();
    for (int e = tid; e < E_; e += blockDim.x) {
        int dst = is64 ? ei[2 * E_ + 2 * e] : ei[E_ + e];
        atomicAdd(&deg[dst], 1);
    }
    __syncthreads();
    if (tid == 0) {
        int acc = 0;
        for (int n = 0; n < C_; n++) { g_rowptr[n] = acc; cur[n] = acc; acc += deg[n]; }
        g_rowptr[C_] = acc;  // == EG_
    }
    __syncthreads();
    for (int e = tid; e < E_; e += blockDim.x) {
        int src = is64 ? ei[2 * e] : ei[e];
        int dst = is64 ? ei[2 * E_ + 2 * e] : ei[E_ + e];
        int p = atomicAdd(&cur[dst], 1);
        g_srcs[p]  = (unsigned short)src;
        g_dstof[p] = (unsigned char)dst;
    }
    __syncthreads();
    for (int n = tid; n < C_; n += blockDim.x) {
        int p = atomicAdd(&cur[n], 1);
        g_srcs[p]  = (unsigned short)n;
        g_dstof[p] = (unsigned char)n;
    }
}

__device__ __forceinline__ float warpSum(float v) {
    #pragma unroll
    for (int o = 16; o > 0; o >>= 1) v += __shfl_xor_sync(0xFFFFFFFFu, v, o);
    return v;
}

// ---------------------------------------------------------------------------
// Main kernel: one CTA (512 threads) per batch.
// ---------------------------------------------------------------------------
__global__ __launch_bounds__(THREADS) void gat_main_kernel(
    const float* __restrict__ x,
    const float* __restrict__ embW, const float* __restrict__ embB,
    const float* __restrict__ lW,   const float* __restrict__ lb,
    const float* __restrict__ rW,   const float* __restrict__ rb,
    const float* __restrict__ att,  const float* __restrict__ gbias,
    const float* __restrict__ lng,  const float* __restrict__ lnb,
    const float* __restrict__ pW,   const float* __restrict__ pb,
    float* __restrict__ out)
{
    extern __shared__ float sm[];
    int*            s_rowptr = (int*)(sm + SM_FLOATS);
    float*          s_att    = (float*)(s_rowptr + 132);
    unsigned short* s_srcs   = (unsigned short*)(s_att + 256);
    unsigned char*  s_dstof  = (unsigned char*)(s_srcs + EG_);

    const int b    = blockIdx.x;
    const int tid  = threadIdx.x;
    const int tx   = tid & 15;        // col group: cols tx + 16*jj, jj<8
    const int ty   = tid >> 4;        // row group: rows ty + 32*ii, ii<4
    const int lane = tid & 31;
    const int warp = tid >> 5;        // 16 warps

    float* attn_out = out + (size_t)B_ * L_ * C_;
    float* myattn   = attn_out + (size_t)b * C_ * C_;

    // --- load CSR + att into smem, zero this batch's attn-map region ---
    for (int i = tid; i <= C_; i += THREADS) s_rowptr[i] = g_rowptr[i];
    for (int i = tid; i < 256; i += THREADS) s_att[i] = att[i];
    for (int i = tid; i < EG_; i += THREADS) { s_srcs[i] = g_srcs[i]; s_dstof[i] = g_dstof[i]; }
    for (int i = tid; i < C_ * C_; i += THREADS) myattn[i] = 0.0f;
    __syncthreads();

    float acc[4][8];

    // ================= Embedding GEMM: h = X_b^T(128x256) @ embW(256x128) + b =========
    #pragma unroll
    for (int ii = 0; ii < 4; ii++)
        #pragma unroll
        for (int jj = 0; jj < 8; jj++) acc[ii][jj] = 0.0f;

    const float* xb = x + (size_t)b * L_ * C_;
    float pA[4], pB[4];
    #pragma unroll
    for (int r = 0; r < 4; r++) {
        int i = tid + THREADS * r;
        int kk = i >> 7, c = i & 127;
        pA[r] = xb[kk * C_ + c];
        pB[r] = embW[kk * HID_ + c];
    }
    for (int k0 = 0; k0 < L_; k0 += 16) {
        #pragma unroll
        for (int r = 0; r < 4; r++) {
            int i = tid + THREADS * r;
            int kk = i >> 7, c = i & 127;
            sm[SM_AS + kk * TS + c] = pA[r];
            sm[SM_BS + kk * TS + c] = pB[r];
        }
        __syncthreads();
        if (k0 + 16 < L_) {
            #pragma unroll
            for (int r = 0; r < 4; r++) {
                int i = tid + THREADS * r;
                int kk = i >> 7, c = i & 127;
                pA[r] = xb[(k0 + 16 + kk) * C_ + c];
                pB[r] = embW[(k0 + 16 + kk) * HID_ + c];
            }
        }
        #pragma unroll
        for (int kk = 0; kk < 16; kk++) {
            float a[4], bb[8];
            #pragma unroll
            for (int ii = 0; ii < 4; ii++) a[ii]  = sm[SM_AS + kk * TS + ty + 32 * ii];
            #pragma unroll
            for (int jj = 0; jj < 8; jj++) bb[jj] = sm[SM_BS + kk * TS + tx + 16 * jj];
            #pragma unroll
            for (int ii = 0; ii < 4; ii++)
                #pragma unroll
                for (int jj = 0; jj < 8; jj++) acc[ii][jj] += a[ii] * bb[jj];
        }
        __syncthreads();
    }
    #pragma unroll
    for (int jj = 0; jj < 8; jj++) {
        float bi = embB[tx + 16 * jj];
        #pragma unroll
        for (int ii = 0; ii < 4; ii++)
            sm[SM_H + (ty + 32 * ii) * HS + tx + 16 * jj] = acc[ii][jj] + bi;
    }
    __syncthreads();

    // ================= Layers =========================================================
    for (int li = 0; li < 2; li++) {
        // --- xl = h @ Wl + bl ; xr = h @ Wr + br (A read from smem h) ---
        for (int which = 0; which < 2; which++) {
            const float* W  = (which == 0 ? lW : rW) + (size_t)li * HID_ * HID_;
            const float* Bv = (which == 0 ? lb : rb) + li * HID_;
            const int dsto  = (which == 0) ? SM_XL : SM_XR;
            #pragma unroll
            for (int ii = 0; ii < 4; ii++)
                #pragma unroll
                for (int jj = 0; jj < 8; jj++) acc[ii][jj] = 0.0f;
            #pragma unroll
            for (int r = 0; r < 4; r++) {
                int i = tid + THREADS * r;
                int kk = i >> 7, c = i & 127;
                pB[r] = W[kk * HID_ + c];
            }
            for (int k0 = 0; k0 < HID_; k0 += 16) {
                #pragma unroll
                for (int r = 0; r < 4; r++) {
                    int i = tid + THREADS * r;
                    int kk = i >> 7, c = i & 127;
                    sm[SM_BS + kk * TS + c] = pB[r];
                }
                __syncthreads();
                if (k0 + 16 < HID_) {
                    #pragma unroll
                    for (int r = 0; r < 4; r++) {
                        int i = tid + THREADS * r;
                        int kk = i >> 7, c = i & 127;
                        pB[r] = W[(k0 + 16 + kk) * HID_ + c];
                    }
                }
                #pragma unroll
                for (int kk = 0; kk < 16; kk++) {
                    float a[4], bb[8];
                    #pragma unroll
                    for (int ii = 0; ii < 4; ii++) a[ii]  = sm[SM_H + (ty + 32 * ii) * HS + k0 + kk];
                    #pragma unroll
                    for (int jj = 0; jj < 8; jj++) bb[jj] = sm[SM_BS + kk * TS + tx + 16 * jj];
                    #pragma unroll
                    for (int ii = 0; ii < 4; ii++)
                        #pragma unroll
                        for (int jj = 0; jj < 8; jj++) acc[ii][jj] += a[ii] * bb[jj];
                }
                __syncthreads();
            }
            #pragma unroll
            for (int jj = 0; jj < 8; jj++) {
                float bi = Bv[tx + 16 * jj];
                #pragma unroll
                for (int ii = 0; ii < 4; ii++)
                    sm[dsto + (ty + 32 * ii) * HS + tx + 16 * jj] = acc[ii][jj] + bi;
            }
            __syncthreads();
        }

        // --- edge phase, one head at a time; GAT output written into freed xr slice ---
        for (int hh = 0; hh < H_; hh++) {
            const float ad = s_att[(li * H_ + hh) * D_ + lane];
            // logits (+ fused exp; no max-subtract needed: |logit| small, exact same ratio)
            for (int e = warp; e < EG_; e += 16) {
                int s = s_srcs[e], d = s_dstof[e];
                float v = sm[SM_XL + s * HS + hh * D_ + lane]
                        + sm[SM_XR + d * HS + hh * D_ + lane];
                v = fmaxf(v, 0.2f * v);            // leaky relu (slope < 1)
                v = warpSum(v * ad);
                v = __expf(v);
                if (lane == 0) sm[SM_LOG + e] = v;
            }
            __syncthreads();
            // softmax-normalize + aggregate: warp per dst node (exclusive row ownership)
            for (int n = warp; n < C_; n += 16) {
                int beg = s_rowptr[n], end = s_rowptr[n + 1];
                float ssum = 0.0f;
                for (int t = beg + lane; t < end; t += 32) ssum += sm[SM_LOG + t];
                ssum = warpSum(ssum);
                float inv = 1.0f / (ssum + 1e-16f);
                float av = 0.0f;
                for (int t = beg; t < end; t++)
                    av += sm[SM_LOG + t] * sm[SM_XL + s_srcs[t] * HS + hh * D_ + lane];
                sm[SM_XR + n * HS + hh * D_ + lane] = av * inv;  // head slice hh of xr dead now
                if (li == 1) {  // final-layer alpha -> attn map (mean over heads)
                    for (int t = beg + lane; t < end; t += 32)
                        atomicAdd(&myattn[n * C_ + s_srcs[t]], sm[SM_LOG + t] * inv * 0.25f);
                }
            }
            __syncthreads();
        }

        // --- bias + ELU + residual + LayerNorm -> h (warp per node) ---
        for (int n = warp; n < C_; n += 16) {
            float v[4];
            float ssum = 0.0f;
            #pragma unroll
            for (int q = 0; q < 4; q++) {
                int j = lane + 32 * q;
                float g = sm[SM_XR + n * HS + j] + gbias[li * HID_ + j];
                g = g > 0.0f ? g : expm1f(g);
                v[q] = sm[SM_H + n * HS + j] + g;
                ssum += v[q];
            }
            ssum = warpSum(ssum);
            float mu = ssum * (1.0f / 128.0f);
            float vs = 0.0f;
            #pragma unroll
            for (int q = 0; q < 4; q++) { float d = v[q] - mu; vs += d * d; }
            vs = warpSum(vs);
            float rstd = rsqrtf(vs * (1.0f / 128.0f) + 1e-5f);
            #pragma unroll
            for (int q = 0; q < 4; q++) {
                int j = lane + 32 * q;
                sm[SM_H + n * HS + j] = (v[q] - mu) * rstd * lng[li * HID_ + j] + lnb[li * HID_ + j];
            }
        }
        __syncthreads();
    }

    // ================= Projection: out[b,l,c] = h[c,:] . pW[:,l] + pb[l] ==============
    for (int half = 0; half < 2; half++) {
        #pragma unroll
        for (int ii = 0; ii < 4; ii++)
            #pragma unroll
            for (int jj = 0; jj < 8; jj++) acc[ii][jj] = 0.0f;
        #pragma unroll
        for (int r = 0; r < 4; r++) {
            int i = tid + THREADS * r;
            int kk = i >> 7, c = i & 127;
            pB[r] = pW[kk * L_ + half * 128 + c];
        }
        for (int k0 = 0; k0 < HID_; k0 += 16) {
            #pragma unroll
            for (int r = 0; r < 4; r++) {
                int i = tid + THREADS * r;
                int kk = i >> 7, c = i & 127;
                sm[SM_BS + kk * TS + c] = pB[r];
            }
            __syncthreads();
            if (k0 + 16 < HID_) {
                #pragma unroll
                for (int r = 0; r < 4; r++) {
                    int i = tid + THREADS * r;
                    int kk = i >> 7, c = i & 127;
                    pB[r] = pW[(k0 + 16 + kk) * L_ + half * 128 + c];
                }
            }
            #pragma unroll
            for (int kk = 0; kk < 16; kk++) {
                float a[4], bb[8];
                #pragma unroll
                for (int ii = 0; ii < 4; ii++) a[ii]  = sm[SM_H + (ty + 32 * ii) * HS + k0 + kk];
                #pragma unroll
                for (int jj = 0; jj < 8; jj++) bb[jj] = sm[SM_BS + kk * TS + tx + 16 * jj];
                #pragma unroll
                for (int ii = 0; ii < 4; ii++)
                    #pragma unroll
                    for (int jj = 0; jj < 8; jj++) acc[ii][jj] += a[ii] * bb[jj];
            }
            __syncthreads();
        }
        // stage into smem (xl buffer, free by now) as [l_local][c] for coalesced writes
        #pragma unroll
        for (int jj = 0; jj < 8; jj++) {
            float bi = pb[half * 128 + tx + 16 * jj];
            #pragma unroll
            for (int ii = 0; ii < 4; ii++)
                sm[SM_XL + (tx + 16 * jj) * HS + ty + 32 * ii] = acc[ii][jj] + bi;
        }
        __syncthreads();
        for (int idx = tid; idx < 128 * C_; idx += THREADS) {
            int ll = idx >> 7, c = idx & 127;
            out[(size_t)b * L_ * C_ + (half * 128 + ll) * C_ + c] = sm[SM_XL + ll * HS + c];
        }
        __syncthreads();
    }
}

// ---------------------------------------------------------------------------
extern "C" void kernel_launch(void* const* d_in, const int* in_sizes, int n_in,
                              void* d_out, int out_size)
{
    const float* x    = (const float*)d_in[0];
    const int*   ei   = (const int*)  d_in[1];   // int32 or int64 (auto-detected)
    const float* embW = (const float*)d_in[2];
    const float* embB = (const float*)d_in[3];
    const float* lW   = (const float*)d_in[4];
    const float* lb   = (const float*)d_in[5];
    const float* rW   = (const float*)d_in[6];
    const float* rb   = (const float*)d_in[7];
    const float* att  = (const float*)d_in[8];
    const float* gb   = (const float*)d_in[9];
    const float* lng  = (const float*)d_in[10];
    const float* lnb  = (const float*)d_in[11];
    const float* pW   = (const float*)d_in[12];
    const float* pb   = (const float*)d_in[13];

    cudaFuncSetAttribute(gat_main_kernel,
                         cudaFuncAttributeMaxDynamicSharedMemorySize, SMEM_BYTES);

    prep_kernel<<<1, 256>>>(ei);
    gat_main_kernel<<<B_, THREADS, SMEM_BYTES>>>(x, embW, embB, lW, lb, rW, rb,
                                                 att, gb, lng, lnb, pW, pb,
                                                 (float*)d_out);
}

// round 7
// speedup vs baseline: 2.4526x; 1.5883x over previous
#include <cuda_runtime.h>
#include <math.h>

namespace {
constexpr int B_   = 256;
constexpr int L_   = 256;
constexpr int C_   = 128;
constexpr int HID_ = 128;
constexpr int H_   = 4;
constexpr int D_   = 32;
constexpr int E_   = 4096;
constexpr int EG_  = E_ + C_;     // 4224 edges per graph incl. self loops

constexpr int THREADS = 1024;

constexpr int HS = 132;           // row stride (floats), 16B-aligned rows
constexpr int TS = 132;           // row stride for GEMM k-tiles

constexpr int SM_H   = 0;                 // h  : 128 x 132
constexpr int SM_XL  = 128 * HS;          // xl : 128 x 132
constexpr int SM_XR  = 2 * 128 * HS;      // xr : 128 x 132
constexpr int SM_AS  = 3 * 128 * HS;      // A tile 16 x 132 (embed only)
constexpr int SM_BS  = SM_AS + 16 * TS;   // B tile 16 x 132
constexpr int SM_FLOATS = SM_AS + 2 * 16 * TS;

constexpr int SMEM_BYTES = SM_FLOATS * 4  // float region
                         + 132 * 4        // rowptr
                         + 256 * 4        // att cache
                         + EG_ * 2        // srcs (u16)
                         + 64;            // pad
}

__device__ int            g_rowptr[C_ + 1];
__device__ unsigned short g_srcs[EG_];

// ---------------------------------------------------------------------------
// Preprocessing: detect int32 vs int64 edge_index, build dst-sorted CSR.
// ---------------------------------------------------------------------------
__global__ void prep_kernel(const int* __restrict__ ei) {
    __shared__ int deg[C_];
    __shared__ int cur[C_];
    __shared__ int s_is64;
    int tid = threadIdx.x;
    if (tid == 0) s_is64 = 1;
    __syncthreads();
    int bad = 0;
    for (int i = tid; i < E_; i += blockDim.x)
        if (ei[2 * i + 1] != 0) bad = 1;
    if (bad) s_is64 = 0;
    __syncthreads();
    const int is64 = s_is64;

    for (int i = tid; i < C_; i += blockDim.x) deg[i] = 1;  // self loop
    __syncthreads();
    for (int e = tid; e < E_; e += blockDim.x) {
        int dst = is64 ? ei[2 * E_ + 2 * e] : ei[E_ + e];
        atomicAdd(&deg[dst], 1);
    }
    __syncthreads();
    if (tid == 0) {
        int acc = 0;
        for (int n = 0; n < C_; n++) { g_rowptr[n] = acc; cur[n] = acc; acc += deg[n]; }
        g_rowptr[C_] = acc;  // == EG_
    }
    __syncthreads();
    for (int e = tid; e < E_; e += blockDim.x) {
        int src = is64 ? ei[2 * e] : ei[e];
        int dst = is64 ? ei[2 * E_ + 2 * e] : ei[E_ + e];
        int p = atomicAdd(&cur[dst], 1);
        g_srcs[p] = (unsigned short)src;
    }
    __syncthreads();
    for (int n = tid; n < C_; n += blockDim.x) {
        int p = atomicAdd(&cur[n], 1);
        g_srcs[p] = (unsigned short)n;
    }
}

__device__ __forceinline__ float warpSum(float v) {
    #pragma unroll
    for (int o = 16; o > 0; o >>= 1) v += __shfl_xor_sync(0xFFFFFFFFu, v, o);
    return v;
}

// ---------------------------------------------------------------------------
// Main kernel: one CTA (1024 threads) per batch.
// GEMM mapping: lane tx = tid&31 -> cols tx*4..tx*4+3 (float4);
//               warp ty = tid>>5 -> rows ty + 32*ii, ii<4. acc[4][4].
// ---------------------------------------------------------------------------
__global__ __launch_bounds__(THREADS) void gat_main_kernel(
    const float* __restrict__ x,
    const float* __restrict__ embW, const float* __restrict__ embB,
    const float* __restrict__ lW,   const float* __restrict__ lb,
    const float* __restrict__ rW,   const float* __restrict__ rb,
    const float* __restrict__ att,  const float* __restrict__ gbias,
    const float* __restrict__ lng,  const float* __restrict__ lnb,
    const float* __restrict__ pW,   const float* __restrict__ pb,
    float* __restrict__ out)
{
    extern __shared__ float sm[];
    int*            s_rowptr = (int*)(sm + SM_FLOATS);
    float*          s_att    = (float*)(s_rowptr + 132);
    unsigned short* s_srcs   = (unsigned short*)(s_att + 256);

    const int b    = blockIdx.x;
    const int tid  = threadIdx.x;
    const int lane = tid & 31;     // tx / edge-phase lane
    const int warp = tid >> 5;     // ty / node owner

    float* attn_out = out + (size_t)B_ * L_ * C_;
    float* myattn   = attn_out + (size_t)b * C_ * C_;

    // --- load CSR + att into smem, zero this batch's attn-map region ---
    for (int i = tid; i <= C_; i += THREADS) s_rowptr[i] = g_rowptr[i];
    for (int i = tid; i < 256; i += THREADS) s_att[i] = att[i];
    for (int i = tid; i < EG_; i += THREADS) s_srcs[i] = g_srcs[i];
    {
        float4 z = make_float4(0.f, 0.f, 0.f, 0.f);
        float4* a4 = (float4*)myattn;
        for (int i = tid; i < C_ * C_ / 4; i += THREADS) a4[i] = z;
    }
    __syncthreads();

    float acc[4][4];

    // ================= Embedding GEMM: h = X_b^T(128x256) @ embW(256x128) + b =========
    #pragma unroll
    for (int ii = 0; ii < 4; ii++)
        #pragma unroll
        for (int q = 0; q < 4; q++) acc[ii][q] = 0.0f;

    const float* xb = x + (size_t)b * L_ * C_;
    float pA[2], pB[2];
    #pragma unroll
    for (int r = 0; r < 2; r++) {
        int i = tid + THREADS * r;
        int kk = i >> 7, c = i & 127;
        pA[r] = xb[kk * C_ + c];
        pB[r] = embW[kk * HID_ + c];
    }
    for (int k0 = 0; k0 < L_; k0 += 16) {
        #pragma unroll
        for (int r = 0; r < 2; r++) {
            int i = tid + THREADS * r;
            int kk = i >> 7, c = i & 127;
            sm[SM_AS + kk * TS + c] = pA[r];
            sm[SM_BS + kk * TS + c] = pB[r];
        }
        __syncthreads();
        if (k0 + 16 < L_) {
            #pragma unroll
            for (int r = 0; r < 2; r++) {
                int i = tid + THREADS * r;
                int kk = i >> 7, c = i & 127;
                pA[r] = xb[(k0 + 16 + kk) * C_ + c];
                pB[r] = embW[(k0 + 16 + kk) * HID_ + c];
            }
        }
        #pragma unroll
        for (int kk = 0; kk < 16; kk++) {
            float4 bv = *(const float4*)&sm[SM_BS + kk * TS + lane * 4];
            float a0 = sm[SM_AS + kk * TS + warp];
            float a1 = sm[SM_AS + kk * TS + warp + 32];
            float a2 = sm[SM_AS + kk * TS + warp + 64];
            float a3 = sm[SM_AS + kk * TS + warp + 96];
            acc[0][0] += a0 * bv.x; acc[0][1] += a0 * bv.y; acc[0][2] += a0 * bv.z; acc[0][3] += a0 * bv.w;
            acc[1][0] += a1 * bv.x; acc[1][1] += a1 * bv.y; acc[1][2] += a1 * bv.z; acc[1][3] += a1 * bv.w;
            acc[2][0] += a2 * bv.x; acc[2][1] += a2 * bv.y; acc[2][2] += a2 * bv.z; acc[2][3] += a2 * bv.w;
            acc[3][0] += a3 * bv.x; acc[3][1] += a3 * bv.y; acc[3][2] += a3 * bv.z; acc[3][3] += a3 * bv.w;
        }
        __syncthreads();
    }
    {
        float4 bi = *(const float4*)&embB[lane * 4];
        #pragma unroll
        for (int ii = 0; ii < 4; ii++) {
            float4 w = make_float4(acc[ii][0] + bi.x, acc[ii][1] + bi.y,
                                   acc[ii][2] + bi.z, acc[ii][3] + bi.w);
            *(float4*)&sm[SM_H + (warp + 32 * ii) * HS + lane * 4] = w;
        }
    }
    __syncthreads();

    // ================= Layers =========================================================
    for (int li = 0; li < 2; li++) {
        // --- xl = h @ Wl + bl ; xr = h @ Wr + br (A broadcast-read from smem h) ---
        for (int which = 0; which < 2; which++) {
            const float* W  = (which == 0 ? lW : rW) + (size_t)li * HID_ * HID_;
            const float* Bv = (which == 0 ? lb : rb) + li * HID_;
            const int dsto  = (which == 0) ? SM_XL : SM_XR;
            #pragma unroll
            for (int ii = 0; ii < 4; ii++)
                #pragma unroll
                for (int q = 0; q < 4; q++) acc[ii][q] = 0.0f;
            #pragma unroll
            for (int r = 0; r < 2; r++) {
                int i = tid + THREADS * r;
                int kk = i >> 7, c = i & 127;
                pB[r] = W[kk * HID_ + c];
            }
            for (int k0 = 0; k0 < HID_; k0 += 16) {
                #pragma unroll
                for (int r = 0; r < 2; r++) {
                    int i = tid + THREADS * r;
                    int kk = i >> 7, c = i & 127;
                    sm[SM_BS + kk * TS + c] = pB[r];
                }
                __syncthreads();
                if (k0 + 16 < HID_) {
                    #pragma unroll
                    for (int r = 0; r < 2; r++) {
                        int i = tid + THREADS * r;
                        int kk = i >> 7, c = i & 127;
                        pB[r] = W[(k0 + 16 + kk) * HID_ + c];
                    }
                }
                #pragma unroll
                for (int kk = 0; kk < 16; kk++) {
                    float4 bv = *(const float4*)&sm[SM_BS + kk * TS + lane * 4];
                    float a0 = sm[SM_H + (warp      ) * HS + k0 + kk];
                    float a1 = sm[SM_H + (warp + 32 ) * HS + k0 + kk];
                    float a2 = sm[SM_H + (warp + 64 ) * HS + k0 + kk];
                    float a3 = sm[SM_H + (warp + 96 ) * HS + k0 + kk];
                    acc[0][0] += a0 * bv.x; acc[0][1] += a0 * bv.y; acc[0][2] += a0 * bv.z; acc[0][3] += a0 * bv.w;
                    acc[1][0] += a1 * bv.x; acc[1][1] += a1 * bv.y; acc[1][2] += a1 * bv.z; acc[1][3] += a1 * bv.w;
                    acc[2][0] += a2 * bv.x; acc[2][1] += a2 * bv.y; acc[2][2] += a2 * bv.z; acc[2][3] += a2 * bv.w;
                    acc[3][0] += a3 * bv.x; acc[3][1] += a3 * bv.y; acc[3][2] += a3 * bv.z; acc[3][3] += a3 * bv.w;
                }
                __syncthreads();
            }
            {
                float4 bi = *(const float4*)&Bv[lane * 4];
                #pragma unroll
                for (int ii = 0; ii < 4; ii++) {
                    float4 w = make_float4(acc[ii][0] + bi.x, acc[ii][1] + bi.y,
                                           acc[ii][2] + bi.z, acc[ii][3] + bi.w);
                    *(float4*)&sm[dsto + (warp + 32 * ii) * HS + lane * 4] = w;
                }
            }
            __syncthreads();
        }

        // --- fused edge phase + LayerNorm: warp owns nodes {warp, warp+32, +64, +96}.
        //     No __syncthreads needed: dst rows exclusively owned; xl read-only.
        for (int n = warp; n < C_; n += 32) {
            const int beg = s_rowptr[n], end = s_rowptr[n + 1];
            const int deg = end - beg;
            int sreg[4];
            #pragma unroll
            for (int ch = 0; ch < 4; ch++) {
                int t = beg + ch * 32 + lane;
                sreg[ch] = (t < end) ? (int)s_srcs[t] : 0;
            }
            float aacc[4] = {0.f, 0.f, 0.f, 0.f};   // per-edge alpha sum over heads

            for (int hh = 0; hh < H_; hh++) {
                const int   ho     = hh * D_;
                const float ad     = s_att[(li * H_ + hh) * D_ + lane];
                const float xr_reg = sm[SM_XR + n * HS + ho + lane];

                float preg[4] = {0.f, 0.f, 0.f, 0.f};
                #pragma unroll
                for (int ch = 0; ch < 4; ch++) {
                    int base = ch * 32;
                    if (base >= deg) break;
                    int lim = min(32, deg - base);
                    #pragma unroll 8
                    for (int j = 0; j < lim; j++) {
                        int s = __shfl_sync(0xFFFFFFFFu, sreg[ch], j);
                        float v = sm[SM_XL + s * HS + ho + lane] + xr_reg;
                        v = fmaxf(v, 0.2f * v);          // leaky relu
                        v = warpSum(v * ad);
                        if (lane == j) preg[ch] = __expf(v);
                    }
                }
                float tot = warpSum(preg[0] + preg[1] + preg[2] + preg[3]);
                float inv = 1.0f / (tot + 1e-16f);

                float av = 0.0f;
                #pragma unroll
                for (int ch = 0; ch < 4; ch++) {
                    int base = ch * 32;
                    if (base >= deg) break;
                    int lim = min(32, deg - base);
                    #pragma unroll 8
                    for (int j = 0; j < lim; j++) {
                        float p = __shfl_sync(0xFFFFFFFFu, preg[ch], j);
                        int   s = __shfl_sync(0xFFFFFFFFu, sreg[ch], j);
                        av += p * sm[SM_XL + s * HS + ho + lane];
                    }
                }
                sm[SM_XR + n * HS + ho + lane] = av * inv;  // head slice of xr now = gat out
                if (li == 1) {
                    #pragma unroll
                    for (int ch = 0; ch < 4; ch++) aacc[ch] += preg[ch] * inv;
                }
            }

            if (li == 1) {  // final-layer alpha -> attn map (mean over heads), 1 atomic/edge
                #pragma unroll
                for (int ch = 0; ch < 4; ch++) {
                    int t = beg + ch * 32 + lane;
                    if (t < end) atomicAdd(&myattn[n * C_ + sreg[ch]], aacc[ch] * 0.25f);
                }
            }

            // --- bias + ELU + residual + LayerNorm for node n (same warp, no sync) ---
            {
                const float4 gb4 = *(const float4*)&gbias[li * HID_ + lane * 4];
                float4 g = *(const float4*)&sm[SM_XR + n * HS + lane * 4];
                float4 h4 = *(const float4*)&sm[SM_H + n * HS + lane * 4];
                float v0 = g.x + gb4.x, v1 = g.y + gb4.y, v2 = g.z + gb4.z, v3 = g.w + gb4.w;
                v0 = v0 > 0.f ? v0 : expm1f(v0);
                v1 = v1 > 0.f ? v1 : expm1f(v1);
                v2 = v2 > 0.f ? v2 : expm1f(v2);
                v3 = v3 > 0.f ? v3 : expm1f(v3);
                v0 += h4.x; v1 += h4.y; v2 += h4.z; v3 += h4.w;
                float mu = warpSum(v0 + v1 + v2 + v3) * (1.0f / 128.0f);
                float d0 = v0 - mu, d1 = v1 - mu, d2 = v2 - mu, d3 = v3 - mu;
                float var = warpSum(d0 * d0 + d1 * d1 + d2 * d2 + d3 * d3) * (1.0f / 128.0f);
                float rstd = rsqrtf(var + 1e-5f);
                const float4 g4 = *(const float4*)&lng[li * HID_ + lane * 4];
                const float4 b4 = *(const float4*)&lnb[li * HID_ + lane * 4];
                float4 o;
                o.x = d0 * rstd * g4.x + b4.x;
                o.y = d1 * rstd * g4.y + b4.y;
                o.z = d2 * rstd * g4.z + b4.z;
                o.w = d3 * rstd * g4.w + b4.w;
                *(float4*)&sm[SM_H + n * HS + lane * 4] = o;
            }
        }
        __syncthreads();
    }

    // ================= Projection: out[b,l,c] = h[c,:] . pW[:,l] + pb[l] ==============
    for (int half = 0; half < 2; half++) {
        #pragma unroll
        for (int ii = 0; ii < 4; ii++)
            #pragma unroll
            for (int q = 0; q < 4; q++) acc[ii][q] = 0.0f;
        #pragma unroll
        for (int r = 0; r < 2; r++) {
            int i = tid + THREADS * r;
            int kk = i >> 7, c = i & 127;
            pB[r] = pW[kk * L_ + half * 128 + c];
        }
        for (int k0 = 0; k0 < HID_; k0 += 16) {
            #pragma unroll
            for (int r = 0; r < 2; r++) {
                int i = tid + THREADS * r;
                int kk = i >> 7, c = i & 127;
                sm[SM_BS + kk * TS + c] = pB[r];
            }
            __syncthreads();
            if (k0 + 16 < HID_) {
                #pragma unroll
                for (int r = 0; r < 2; r++) {
                    int i = tid + THREADS * r;
                    int kk = i >> 7, c = i & 127;
                    pB[r] = pW[(k0 + 16 + kk) * L_ + half * 128 + c];
                }
            }
            #pragma unroll
            for (int kk = 0; kk < 16; kk++) {
                float4 bv = *(const float4*)&sm[SM_BS + kk * TS + lane * 4];
                float a0 = sm[SM_H + (warp      ) * HS + k0 + kk];
                float a1 = sm[SM_H + (warp + 32 ) * HS + k0 + kk];
                float a2 = sm[SM_H + (warp + 64 ) * HS + k0 + kk];
                float a3 = sm[SM_H + (warp + 96 ) * HS + k0 + kk];
                acc[0][0] += a0 * bv.x; acc[0][1] += a0 * bv.y; acc[0][2] += a0 * bv.z; acc[0][3] += a0 * bv.w;
                acc[1][0] += a1 * bv.x; acc[1][1] += a1 * bv.y; acc[1][2] += a1 * bv.z; acc[1][3] += a1 * bv.w;
                acc[2][0] += a2 * bv.x; acc[2][1] += a2 * bv.y; acc[2][2] += a2 * bv.z; acc[2][3] += a2 * bv.w;
                acc[3][0] += a3 * bv.x; acc[3][1] += a3 * bv.y; acc[3][2] += a3 * bv.z; acc[3][3] += a3 * bv.w;
            }
            __syncthreads();
        }
        // stage as T[c][l_local] (float4, conflict-free stores), then coalesced write
        {
            float4 bi = *(const float4*)&pb[half * 128 + lane * 4];
            #pragma unroll
            for (int ii = 0; ii < 4; ii++) {
                float4 w = make_float4(acc[ii][0] + bi.x, acc[ii][1] + bi.y,
                                       acc[ii][2] + bi.z, acc[ii][3] + bi.w);
                *(float4*)&sm[SM_XL + (warp + 32 * ii) * HS + lane * 4] = w;
            }
        }
        __syncthreads();
        for (int idx = tid; idx < 128 * C_; idx += THREADS) {
            int ll = idx >> 7, c = idx & 127;
            out[(size_t)b * L_ * C_ + (half * 128 + ll) * C_ + c] = sm[SM_XL + c * HS + ll];
        }
        __syncthreads();
    }
}

// ---------------------------------------------------------------------------
extern "C" void kernel_launch(void* const* d_in, const int* in_sizes, int n_in,
                              void* d_out, int out_size)
{
    const float* x    = (const float*)d_in[0];
    const int*   ei   = (const int*)  d_in[1];   // int32 or int64 (auto-detected)
    const float* embW = (const float*)d_in[2];
    const float* embB = (const float*)d_in[3];
    const float* lW   = (const float*)d_in[4];
    const float* lb   = (const float*)d_in[5];
    const float* rW   = (const float*)d_in[6];
    const float* rb   = (const float*)d_in[7];
    const float* att  = (const float*)d_in[8];
    const float* gb   = (const float*)d_in[9];
    const float* lng  = (const float*)d_in[10];
    const float* lnb  = (const float*)d_in[11];
    const float* pW   = (const float*)d_in[12];
    const float* pb   = (const float*)d_in[13];

    cudaFuncSetAttribute(gat_main_kernel,
                         cudaFuncAttributeMaxDynamicSharedMemorySize, SMEM_BYTES);

    prep_kernel<<<1, 256>>>(ei);
    gat_main_kernel<<<B_, THREADS, SMEM_BYTES>>>(x, embW, embB, lW, lb, rW, rb,
                                                 att, gb, lng, lnb, pW, pb,
                                                 (float*)d_out);
}

// round 8
// speedup vs baseline: 3.8596x; 1.5737x over previous
#include <cuda_runtime.h>
#include <math.h>

namespace {
constexpr int B_   = 256;
constexpr int L_   = 256;
constexpr int C_   = 128;
constexpr int HID_ = 128;
constexpr int H_   = 4;
constexpr int D_   = 32;
constexpr int E_   = 4096;
constexpr int EG_  = E_ + C_;     // 4224 edges per graph incl. self loops

constexpr int THREADS = 1024;

constexpr int HS = 132;           // row stride (floats), 16B-aligned rows
constexpr int TS = 132;           // row stride for GEMM k-tiles

constexpr int SM_H   = 0;                 // h  : 128 x 132
constexpr int SM_XL  = 128 * HS;          // xl : 128 x 132
constexpr int SM_XR  = 2 * 128 * HS;      // xr : 128 x 132
constexpr int SM_AS  = 3 * 128 * HS;      // A tile 16 x 132 (embed only)
constexpr int SM_BS  = SM_AS + 16 * TS;   // B tile 16 x 132
constexpr int SM_FLOATS = SM_AS + 2 * 16 * TS;

constexpr int SMEM_BYTES = SM_FLOATS * 4  // float region
                         + 132 * 4        // rowptr
                         + 256 * 4        // att cache
                         + EG_ * 2        // srcs (u16)
                         + 64;            // pad
}

__device__ int            g_rowptr[C_ + 1];
__device__ unsigned short g_srcs[EG_];

// ---------------------------------------------------------------------------
// Preprocessing: detect int32 vs int64 edge_index, build dst-sorted CSR.
// ---------------------------------------------------------------------------
__global__ void prep_kernel(const int* __restrict__ ei) {
    __shared__ int deg[C_];
    __shared__ int cur[C_];
    __shared__ int s_is64;
    int tid = threadIdx.x;
    if (tid == 0) s_is64 = 1;
    __syncthreads();
    int bad = 0;
    for (int i = tid; i < E_; i += blockDim.x)
        if (ei[2 * i + 1] != 0) bad = 1;
    if (bad) s_is64 = 0;
    __syncthreads();
    const int is64 = s_is64;

    for (int i = tid; i < C_; i += blockDim.x) deg[i] = 1;  // self loop
    __syncthreads();
    for (int e = tid; e < E_; e += blockDim.x) {
        int dst = is64 ? ei[2 * E_ + 2 * e] : ei[E_ + e];
        atomicAdd(&deg[dst], 1);
    }
    __syncthreads();
    if (tid == 0) {
        int acc = 0;
        for (int n = 0; n < C_; n++) { g_rowptr[n] = acc; cur[n] = acc; acc += deg[n]; }
        g_rowptr[C_] = acc;  // == EG_
    }
    __syncthreads();
    for (int e = tid; e < E_; e += blockDim.x) {
        int src = is64 ? ei[2 * e] : ei[e];
        int dst = is64 ? ei[2 * E_ + 2 * e] : ei[E_ + e];
        int p = atomicAdd(&cur[dst], 1);
        g_srcs[p] = (unsigned short)src;
    }
    __syncthreads();
    for (int n = tid; n < C_; n += blockDim.x) {
        int p = atomicAdd(&cur[n], 1);
        g_srcs[p] = (unsigned short)n;
    }
}

__device__ __forceinline__ float warpSum(float v) {
    #pragma unroll
    for (int o = 16; o > 0; o >>= 1) v += __shfl_xor_sync(0xFFFFFFFFu, v, o);
    return v;
}

// ---------------------------------------------------------------------------
// Main kernel: one CTA (1024 threads) per batch.
// GEMM mapping: lane -> cols lane*4..+3 (float4); warp -> rows warp + 32*ii.
// Edge phase: lane covers feature dims 4*lane..4*lane+3 => head = lane>>3;
// all 4 heads processed in one fused pass per edge (segmented 8-lane reduce).
// ---------------------------------------------------------------------------
__global__ __launch_bounds__(THREADS) void gat_main_kernel(
    const float* __restrict__ x,
    const float* __restrict__ embW, const float* __restrict__ embB,
    const float* __restrict__ lW,   const float* __restrict__ lb,
    const float* __restrict__ rW,   const float* __restrict__ rb,
    const float* __restrict__ att,  const float* __restrict__ gbias,
    const float* __restrict__ lng,  const float* __restrict__ lnb,
    const float* __restrict__ pW,   const float* __restrict__ pb,
    float* __restrict__ out)
{
    extern __shared__ float sm[];
    int*            s_rowptr = (int*)(sm + SM_FLOATS);
    float*          s_att    = (float*)(s_rowptr + 132);
    unsigned short* s_srcs   = (unsigned short*)(s_att + 256);

    const int b    = blockIdx.x;
    const int tid  = threadIdx.x;
    const int lane = tid & 31;
    const int warp = tid >> 5;

    float* attn_out = out + (size_t)B_ * L_ * C_;
    float* myattn   = attn_out + (size_t)b * C_ * C_;

    // --- load CSR + att into smem, zero this batch's attn-map region ---
    for (int i = tid; i <= C_; i += THREADS) s_rowptr[i] = g_rowptr[i];
    for (int i = tid; i < 256; i += THREADS) s_att[i] = att[i];
    for (int i = tid; i < EG_; i += THREADS) s_srcs[i] = g_srcs[i];
    {
        float4 z = make_float4(0.f, 0.f, 0.f, 0.f);
        float4* a4 = (float4*)myattn;
        for (int i = tid; i < C_ * C_ / 4; i += THREADS) a4[i] = z;
    }
    __syncthreads();

    float acc[4][4];

    // ================= Embedding GEMM: h = X_b^T(128x256) @ embW(256x128) + b =========
    #pragma unroll
    for (int ii = 0; ii < 4; ii++)
        #pragma unroll
        for (int q = 0; q < 4; q++) acc[ii][q] = 0.0f;

    const float* xb = x + (size_t)b * L_ * C_;
    float pA[2], pB[2];
    #pragma unroll
    for (int r = 0; r < 2; r++) {
        int i = tid + THREADS * r;
        int kk = i >> 7, c = i & 127;
        pA[r] = xb[kk * C_ + c];
        pB[r] = embW[kk * HID_ + c];
    }
    for (int k0 = 0; k0 < L_; k0 += 16) {
        #pragma unroll
        for (int r = 0; r < 2; r++) {
            int i = tid + THREADS * r;
            int kk = i >> 7, c = i & 127;
            sm[SM_AS + kk * TS + c] = pA[r];
            sm[SM_BS + kk * TS + c] = pB[r];
        }
        __syncthreads();
        if (k0 + 16 < L_) {
            #pragma unroll
            for (int r = 0; r < 2; r++) {
                int i = tid + THREADS * r;
                int kk = i >> 7, c = i & 127;
                pA[r] = xb[(k0 + 16 + kk) * C_ + c];
                pB[r] = embW[(k0 + 16 + kk) * HID_ + c];
            }
        }
        #pragma unroll
        for (int kk = 0; kk < 16; kk++) {
            float4 bv = *(const float4*)&sm[SM_BS + kk * TS + lane * 4];
            float a0 = sm[SM_AS + kk * TS + warp];
            float a1 = sm[SM_AS + kk * TS + warp + 32];
            float a2 = sm[SM_AS + kk * TS + warp + 64];
            float a3 = sm[SM_AS + kk * TS + warp + 96];
            acc[0][0] += a0 * bv.x; acc[0][1] += a0 * bv.y; acc[0][2] += a0 * bv.z; acc[0][3] += a0 * bv.w;
            acc[1][0] += a1 * bv.x; acc[1][1] += a1 * bv.y; acc[1][2] += a1 * bv.z; acc[1][3] += a1 * bv.w;
            acc[2][0] += a2 * bv.x; acc[2][1] += a2 * bv.y; acc[2][2] += a2 * bv.z; acc[2][3] += a2 * bv.w;
            acc[3][0] += a3 * bv.x; acc[3][1] += a3 * bv.y; acc[3][2] += a3 * bv.z; acc[3][3] += a3 * bv.w;
        }
        __syncthreads();
    }
    {
        float4 bi = *(const float4*)&embB[lane * 4];
        #pragma unroll
        for (int ii = 0; ii < 4; ii++) {
            float4 w = make_float4(acc[ii][0] + bi.x, acc[ii][1] + bi.y,
                                   acc[ii][2] + bi.z, acc[ii][3] + bi.w);
            *(float4*)&sm[SM_H + (warp + 32 * ii) * HS + lane * 4] = w;
        }
    }
    __syncthreads();

    // ================= Layers =========================================================
    for (int li = 0; li < 2; li++) {
        // --- xl = h @ Wl + bl ; xr = h @ Wr + br (A broadcast-read from smem h) ---
        for (int which = 0; which < 2; which++) {
            const float* W  = (which == 0 ? lW : rW) + (size_t)li * HID_ * HID_;
            const float* Bv = (which == 0 ? lb : rb) + li * HID_;
            const int dsto  = (which == 0) ? SM_XL : SM_XR;
            #pragma unroll
            for (int ii = 0; ii < 4; ii++)
                #pragma unroll
                for (int q = 0; q < 4; q++) acc[ii][q] = 0.0f;
            #pragma unroll
            for (int r = 0; r < 2; r++) {
                int i = tid + THREADS * r;
                int kk = i >> 7, c = i & 127;
                pB[r] = W[kk * HID_ + c];
            }
            for (int k0 = 0; k0 < HID_; k0 += 16) {
                #pragma unroll
                for (int r = 0; r < 2; r++) {
                    int i = tid + THREADS * r;
                    int kk = i >> 7, c = i & 127;
                    sm[SM_BS + kk * TS + c] = pB[r];
                }
                __syncthreads();
                if (k0 + 16 < HID_) {
                    #pragma unroll
                    for (int r = 0; r < 2; r++) {
                        int i = tid + THREADS * r;
                        int kk = i >> 7, c = i & 127;
                        pB[r] = W[(k0 + 16 + kk) * HID_ + c];
                    }
                }
                #pragma unroll
                for (int kk = 0; kk < 16; kk++) {
                    float4 bv = *(const float4*)&sm[SM_BS + kk * TS + lane * 4];
                    float a0 = sm[SM_H + (warp      ) * HS + k0 + kk];
                    float a1 = sm[SM_H + (warp + 32 ) * HS + k0 + kk];
                    float a2 = sm[SM_H + (warp + 64 ) * HS + k0 + kk];
                    float a3 = sm[SM_H + (warp + 96 ) * HS + k0 + kk];
                    acc[0][0] += a0 * bv.x; acc[0][1] += a0 * bv.y; acc[0][2] += a0 * bv.z; acc[0][3] += a0 * bv.w;
                    acc[1][0] += a1 * bv.x; acc[1][1] += a1 * bv.y; acc[1][2] += a1 * bv.z; acc[1][3] += a1 * bv.w;
                    acc[2][0] += a2 * bv.x; acc[2][1] += a2 * bv.y; acc[2][2] += a2 * bv.z; acc[2][3] += a2 * bv.w;
                    acc[3][0] += a3 * bv.x; acc[3][1] += a3 * bv.y; acc[3][2] += a3 * bv.z; acc[3][3] += a3 * bv.w;
                }
                __syncthreads();
            }
            {
                float4 bi = *(const float4*)&Bv[lane * 4];
                #pragma unroll
                for (int ii = 0; ii < 4; ii++) {
                    float4 w = make_float4(acc[ii][0] + bi.x, acc[ii][1] + bi.y,
                                           acc[ii][2] + bi.z, acc[ii][3] + bi.w);
                    *(float4*)&sm[dsto + (warp + 32 * ii) * HS + lane * 4] = w;
                }
            }
            __syncthreads();
        }

        // --- fused edge phase (all 4 heads at once) + LayerNorm.
        //     Warp owns nodes {warp, warp+32, +64, +96}; no __syncthreads needed.
        {
            const float4 a4 = *(const float4*)&s_att[li * 128 + lane * 4];

            for (int n = warp; n < C_; n += 32) {
                const int beg = s_rowptr[n], end = s_rowptr[n + 1];
                const int deg = end - beg;
                int sreg[4];
                #pragma unroll
                for (int ch = 0; ch < 4; ch++) {
                    int t = beg + ch * 32 + lane;
                    sreg[ch] = (t < end) ? (int)s_srcs[t] : 0;
                }
                const float4 xr4 = *(const float4*)&sm[SM_XR + n * HS + lane * 4];

                float4 av = make_float4(0.f, 0.f, 0.f, 0.f);
                float psum = 0.0f;

                #pragma unroll
                for (int ch = 0; ch < 4; ch++) {
                    int base = ch * 32;
                    if (base >= deg) break;
                    int lim = min(32, deg - base);
                    #pragma unroll 8
                    for (int j = 0; j < lim; j++) {
                        int s = __shfl_sync(0xFFFFFFFFu, sreg[ch], j);
                        float4 xlv = *(const float4*)&sm[SM_XL + s * HS + lane * 4];
                        float vx = xlv.x + xr4.x; vx = fmaxf(vx, 0.2f * vx);
                        float vy = xlv.y + xr4.y; vy = fmaxf(vy, 0.2f * vy);
                        float vz = xlv.z + xr4.z; vz = fmaxf(vz, 0.2f * vz);
                        float vw = xlv.w + xr4.w; vw = fmaxf(vw, 0.2f * vw);
                        float t = vx * a4.x + vy * a4.y + vz * a4.z + vw * a4.w;
                        // segmented sum over the 8 lanes of this head
                        t += __shfl_xor_sync(0xFFFFFFFFu, t, 4);
                        t += __shfl_xor_sync(0xFFFFFFFFu, t, 2);
                        t += __shfl_xor_sync(0xFFFFFFFFu, t, 1);
                        float p = __expf(t);       // p of this lane's head
                        psum += p;
                        av.x += p * xlv.x; av.y += p * xlv.y;
                        av.z += p * xlv.z; av.w += p * xlv.w;
                    }
                }
                const float inv = 1.0f / (psum + 1e-16f);
                av.x *= inv; av.y *= inv; av.z *= inv; av.w *= inv;
                *(float4*)&sm[SM_XR + n * HS + lane * 4] = av;   // gat out for node n

                if (li == 1) {
                    // recompute p per edge; attn map gets mean over heads of alpha
                    float aacc[4] = {0.f, 0.f, 0.f, 0.f};
                    #pragma unroll
                    for (int ch = 0; ch < 4; ch++) {
                        int base = ch * 32;
                        if (base >= deg) break;
                        int lim = min(32, deg - base);
                        #pragma unroll 8
                        for (int j = 0; j < lim; j++) {
                            int s = __shfl_sync(0xFFFFFFFFu, sreg[ch], j);
                            float4 xlv = *(const float4*)&sm[SM_XL + s * HS + lane * 4];
                            float vx = xlv.x + xr4.x; vx = fmaxf(vx, 0.2f * vx);
                            float vy = xlv.y + xr4.y; vy = fmaxf(vy, 0.2f * vy);
                            float vz = xlv.z + xr4.z; vz = fmaxf(vz, 0.2f * vz);
                            float vw = xlv.w + xr4.w; vw = fmaxf(vw, 0.2f * vw);
                            float t = vx * a4.x + vy * a4.y + vz * a4.z + vw * a4.w;
                            t += __shfl_xor_sync(0xFFFFFFFFu, t, 4);
                            t += __shfl_xor_sync(0xFFFFFFFFu, t, 2);
                            t += __shfl_xor_sync(0xFFFFFFFFu, t, 1);
                            float pin = __expf(t) * inv;
                            // sum across the 4 heads (groups of 8)
                            pin += __shfl_xor_sync(0xFFFFFFFFu, pin, 8);
                            pin += __shfl_xor_sync(0xFFFFFFFFu, pin, 16);
                            if (lane == j) aacc[ch] = pin;
                        }
                    }
                    #pragma unroll
                    for (int ch = 0; ch < 4; ch++) {
                        int t = beg + ch * 32 + lane;
                        if (t < end) atomicAdd(&myattn[n * C_ + sreg[ch]], aacc[ch] * 0.25f);
                    }
                }

                // --- bias + ELU + residual + LayerNorm for node n (same warp) ---
                {
                    const float4 gb4 = *(const float4*)&gbias[li * HID_ + lane * 4];
                    float4 h4 = *(const float4*)&sm[SM_H + n * HS + lane * 4];
                    float v0 = av.x + gb4.x, v1 = av.y + gb4.y, v2 = av.z + gb4.z, v3 = av.w + gb4.w;
                    v0 = v0 > 0.f ? v0 : expm1f(v0);
                    v1 = v1 > 0.f ? v1 : expm1f(v1);
                    v2 = v2 > 0.f ? v2 : expm1f(v2);
                    v3 = v3 > 0.f ? v3 : expm1f(v3);
                    v0 += h4.x; v1 += h4.y; v2 += h4.z; v3 += h4.w;
                    float mu = warpSum(v0 + v1 + v2 + v3) * (1.0f / 128.0f);
                    float d0 = v0 - mu, d1 = v1 - mu, d2 = v2 - mu, d3 = v3 - mu;
                    float var = warpSum(d0 * d0 + d1 * d1 + d2 * d2 + d3 * d3) * (1.0f / 128.0f);
                    float rstd = rsqrtf(var + 1e-5f);
                    const float4 g4 = *(const float4*)&lng[li * HID_ + lane * 4];
                    const float4 b4 = *(const float4*)&lnb[li * HID_ + lane * 4];
                    float4 o;
                    o.x = d0 * rstd * g4.x + b4.x;
                    o.y = d1 * rstd * g4.y + b4.y;
                    o.z = d2 * rstd * g4.z + b4.z;
                    o.w = d3 * rstd * g4.w + b4.w;
                    *(float4*)&sm[SM_H + n * HS + lane * 4] = o;
                }
            }
        }
        __syncthreads();
    }

    // ================= Projection: out[b,l,c] = h[c,:] . pW[:,l] + pb[l] ==============
    for (int half = 0; half < 2; half++) {
        #pragma unroll
        for (int ii = 0; ii < 4; ii++)
            #pragma unroll
            for (int q = 0; q < 4; q++) acc[ii][q] = 0.0f;
        #pragma unroll
        for (int r = 0; r < 2; r++) {
            int i = tid + THREADS * r;
            int kk = i >> 7, c = i & 127;
            pB[r] = pW[kk * L_ + half * 128 + c];
        }
        for (int k0 = 0; k0 < HID_; k0 += 16) {
            #pragma unroll
            for (int r = 0; r < 2; r++) {
                int i = tid + THREADS * r;
                int kk = i >> 7, c = i & 127;
                sm[SM_BS + kk * TS + c] = pB[r];
            }
            __syncthreads();
            if (k0 + 16 < HID_) {
                #pragma unroll
                for (int r = 0; r < 2; r++) {
                    int i = tid + THREADS * r;
                    int kk = i >> 7, c = i & 127;
                    pB[r] = pW[(k0 + 16 + kk) * L_ + half * 128 + c];
                }
            }
            #pragma unroll
            for (int kk = 0; kk < 16; kk++) {
                float4 bv = *(const float4*)&sm[SM_BS + kk * TS + lane * 4];
                float a0 = sm[SM_H + (warp      ) * HS + k0 + kk];
                float a1 = sm[SM_H + (warp + 32 ) * HS + k0 + kk];
                float a2 = sm[SM_H + (warp + 64 ) * HS + k0 + kk];
                float a3 = sm[SM_H + (warp + 96 ) * HS + k0 + kk];
                acc[0][0] += a0 * bv.x; acc[0][1] += a0 * bv.y; acc[0][2] += a0 * bv.z; acc[0][3] += a0 * bv.w;
                acc[1][0] += a1 * bv.x; acc[1][1] += a1 * bv.y; acc[1][2] += a1 * bv.z; acc[1][3] += a1 * bv.w;
                acc[2][0] += a2 * bv.x; acc[2][1] += a2 * bv.y; acc[2][2] += a2 * bv.z; acc[2][3] += a2 * bv.w;
                acc[3][0] += a3 * bv.x; acc[3][1] += a3 * bv.y; acc[3][2] += a3 * bv.z; acc[3][3] += a3 * bv.w;
            }
            __syncthreads();
        }
        // stage as T[c][l_local] (float4, conflict-free stores), then coalesced write
        {
            float4 bi = *(const float4*)&pb[half * 128 + lane * 4];
            #pragma unroll
            for (int ii = 0; ii < 4; ii++) {
                float4 w = make_float4(acc[ii][0] + bi.x, acc[ii][1] + bi.y,
                                       acc[ii][2] + bi.z, acc[ii][3] + bi.w);
                *(float4*)&sm[SM_XL + (warp + 32 * ii) * HS + lane * 4] = w;
            }
        }
        __syncthreads();
        for (int idx = tid; idx < 128 * C_; idx += THREADS) {
            int ll = idx >> 7, c = idx & 127;
            out[(size_t)b * L_ * C_ + (half * 128 + ll) * C_ + c] = sm[SM_XL + c * HS + ll];
        }
        __syncthreads();
    }
}

// ---------------------------------------------------------------------------
extern "C" void kernel_launch(void* const* d_in, const int* in_sizes, int n_in,
                              void* d_out, int out_size)
{
    const float* x    = (const float*)d_in[0];
    const int*   ei   = (const int*)  d_in[1];   // int32 or int64 (auto-detected)
    const float* embW = (const float*)d_in[2];
    const float* embB = (const float*)d_in[3];
    const float* lW   = (const float*)d_in[4];
    const float* lb   = (const float*)d_in[5];
    const float* rW   = (const float*)d_in[6];
    const float* rb   = (const float*)d_in[7];
    const float* att  = (const float*)d_in[8];
    const float* gb   = (const float*)d_in[9];
    const float* lng  = (const float*)d_in[10];
    const float* lnb  = (const float*)d_in[11];
    const float* pW   = (const float*)d_in[12];
    const float* pb   = (const float*)d_in[13];

    cudaFuncSetAttribute(gat_main_kernel,
                         cudaFuncAttributeMaxDynamicSharedMemorySize, SMEM_BYTES);

    prep_kernel<<<1, 256>>>(ei);
    gat_main_kernel<<<B_, THREADS, SMEM_BYTES>>>(x, embW, embB, lW, lb, rW, rb,
                                                 att, gb, lng, lnb, pW, pb,
                                                 (float*)d_out);
}

// round 9
// speedup vs baseline: 3.9507x; 1.0236x over previous
#include <cuda_runtime.h>
#include <math.h>

namespace {
constexpr int B_   = 256;
constexpr int L_   = 256;
constexpr int C_   = 128;
constexpr int HID_ = 128;
constexpr int H_   = 4;
constexpr int D_   = 32;
constexpr int E_   = 4096;
constexpr int EG_  = E_ + C_;     // 4224 edges per graph incl. self loops

constexpr int THREADS = 1024;

constexpr int HS = 132;           // row stride (floats), 16B-aligned rows
constexpr int TS = 132;           // row stride for GEMM k-tiles (528B = 16B-aligned)

constexpr int SM_H   = 0;                 // h  : 128 x 132
constexpr int SM_XL  = 128 * HS;          // xl : 128 x 132
constexpr int SM_XR  = 2 * 128 * HS;      // xr : 128 x 132
constexpr int SM_AS  = 3 * 128 * HS;      // tile buffer 0 / embed A tile
constexpr int SM_BS  = SM_AS + 16 * TS;   // tile buffer 1 / embed B tile
constexpr int SM_FLOATS = SM_AS + 2 * 16 * TS;

constexpr int SMEM_BYTES = SM_FLOATS * 4  // float region
                         + 132 * 4        // rowptr
                         + 256 * 4        // att cache
                         + EG_ * 2        // srcs (u16)
                         + 64;            // pad
}

__device__ int            g_rowptr[C_ + 1];
__device__ unsigned short g_srcs[EG_];

// ---------------------------------------------------------------------------
// Packed f32x2 helpers (FFMA2 — only reachable via PTX on sm_103a)
// ---------------------------------------------------------------------------
__device__ __forceinline__ unsigned long long dup2(float v) {
    unsigned long long r;
    asm("mov.b64 %0, {%1, %1};" : "=l"(r) : "f"(v));
    return r;
}
__device__ __forceinline__ void ffma2(unsigned long long& d,
                                      unsigned long long a, unsigned long long b) {
    asm("fma.rn.f32x2 %0, %1, %2, %3;" : "=l"(d) : "l"(a), "l"(b), "l"(d));
}
__device__ __forceinline__ float2 unpack2(unsigned long long v) {
    float2 f;
    asm("mov.b64 {%0, %1}, %2;" : "=f"(f.x), "=f"(f.y) : "l"(v));
    return f;
}

// ---------------------------------------------------------------------------
// Preprocessing: detect int32 vs int64 edge_index, build dst-sorted CSR.
// ---------------------------------------------------------------------------
__global__ void prep_kernel(const int* __restrict__ ei) {
    __shared__ int deg[C_];
    __shared__ int cur[C_];
    __shared__ int s_is64;
    int tid = threadIdx.x;
    if (tid == 0) s_is64 = 1;
    __syncthreads();
    int bad = 0;
    for (int i = tid; i < E_; i += blockDim.x)
        if (ei[2 * i + 1] != 0) bad = 1;
    if (bad) s_is64 = 0;
    __syncthreads();
    const int is64 = s_is64;

    for (int i = tid; i < C_; i += blockDim.x) deg[i] = 1;  // self loop
    __syncthreads();
    for (int e = tid; e < E_; e += blockDim.x) {
        int dst = is64 ? ei[2 * E_ + 2 * e] : ei[E_ + e];
        atomicAdd(&deg[dst], 1);
    }
    __syncthreads();
    if (tid == 0) {
        int acc = 0;
        for (int n = 0; n < C_; n++) { g_rowptr[n] = acc; cur[n] = acc; acc += deg[n]; }
        g_rowptr[C_] = acc;  // == EG_
    }
    __syncthreads();
    for (int e = tid; e < E_; e += blockDim.x) {
        int src = is64 ? ei[2 * e] : ei[e];
        int dst = is64 ? ei[2 * E_ + 2 * e] : ei[E_ + e];
        int p = atomicAdd(&cur[dst], 1);
        g_srcs[p] = (unsigned short)src;
    }
    __syncthreads();
    for (int n = tid; n < C_; n += blockDim.x) {
        int p = atomicAdd(&cur[n], 1);
        g_srcs[p] = (unsigned short)n;
    }
}

__device__ __forceinline__ float warpSum(float v) {
    #pragma unroll
    for (int o = 16; o > 0; o >>= 1) v += __shfl_xor_sync(0xFFFFFFFFu, v, o);
    return v;
}

// ---------------------------------------------------------------------------
// Main kernel: one CTA (1024 threads) per batch.
// GEMM: lane -> cols lane*4..+3 (2 packed f32x2 accumulators per row);
//       warp -> rows warp + 32*ii, ii<4. FFMA2 inner loop.
// Edge phase: lane covers dims 4*lane..+3 => head = lane>>3; one fused pass.
// ---------------------------------------------------------------------------
__global__ __launch_bounds__(THREADS) void gat_main_kernel(
    const float* __restrict__ x,
    const float* __restrict__ embW, const float* __restrict__ embB,
    const float* __restrict__ lW,   const float* __restrict__ lb,
    const float* __restrict__ rW,   const float* __restrict__ rb,
    const float* __restrict__ att,  const float* __restrict__ gbias,
    const float* __restrict__ lng,  const float* __restrict__ lnb,
    const float* __restrict__ pW,   const float* __restrict__ pb,
    float* __restrict__ out)
{
    extern __shared__ float sm[];
    int*            s_rowptr = (int*)(sm + SM_FLOATS);
    float*          s_att    = (float*)(s_rowptr + 132);
    unsigned short* s_srcs   = (unsigned short*)(s_att + 256);

    const int b    = blockIdx.x;
    const int tid  = threadIdx.x;
    const int lane = tid & 31;
    const int warp = tid >> 5;

    float* attn_out = out + (size_t)B_ * L_ * C_;
    float* myattn   = attn_out + (size_t)b * C_ * C_;

    // --- load CSR + att into smem, zero this batch's attn-map region ---
    for (int i = tid; i <= C_; i += THREADS) s_rowptr[i] = g_rowptr[i];
    for (int i = tid; i < 256; i += THREADS) s_att[i] = att[i];
    for (int i = tid; i < EG_; i += THREADS) s_srcs[i] = g_srcs[i];
    {
        float4 z = make_float4(0.f, 0.f, 0.f, 0.f);
        float4* a4 = (float4*)myattn;
        for (int i = tid; i < C_ * C_ / 4; i += THREADS) a4[i] = z;
    }
    __syncthreads();

    unsigned long long acc2[4][2];
    float pA[2], pB[2];

    // ================= Embedding GEMM: h = X_b^T(128x256) @ embW(256x128) + b =========
    #pragma unroll
    for (int ii = 0; ii < 4; ii++) { acc2[ii][0] = 0ull; acc2[ii][1] = 0ull; }

    const float* xb = x + (size_t)b * L_ * C_;
    #pragma unroll
    for (int r = 0; r < 2; r++) {
        int i = tid + THREADS * r;
        int kk = i >> 7, c = i & 127;
        pA[r] = xb[kk * C_ + c];
        pB[r] = embW[kk * HID_ + c];
    }
    for (int k0 = 0; k0 < L_; k0 += 16) {
        #pragma unroll
        for (int r = 0; r < 2; r++) {
            int i = tid + THREADS * r;
            int kk = i >> 7, c = i & 127;
            sm[SM_AS + kk * TS + c] = pA[r];
            sm[SM_BS + kk * TS + c] = pB[r];
        }
        __syncthreads();
        if (k0 + 16 < L_) {
            #pragma unroll
            for (int r = 0; r < 2; r++) {
                int i = tid + THREADS * r;
                int kk = i >> 7, c = i & 127;
                pA[r] = xb[(k0 + 16 + kk) * C_ + c];
                pB[r] = embW[(k0 + 16 + kk) * HID_ + c];
            }
        }
        #pragma unroll
        for (int kk = 0; kk < 16; kk++) {
            ulonglong2 bv = *(const ulonglong2*)&sm[SM_BS + kk * TS + lane * 4];
            #pragma unroll
            for (int ii = 0; ii < 4; ii++) {
                unsigned long long ad = dup2(sm[SM_AS + kk * TS + warp + 32 * ii]);
                ffma2(acc2[ii][0], ad, bv.x);
                ffma2(acc2[ii][1], ad, bv.y);
            }
        }
        __syncthreads();
    }
    {
        float4 bi = *(const float4*)&embB[lane * 4];
        #pragma unroll
        for (int ii = 0; ii < 4; ii++) {
            float2 lo = unpack2(acc2[ii][0]), hi = unpack2(acc2[ii][1]);
            float4 w = make_float4(lo.x + bi.x, lo.y + bi.y, hi.x + bi.z, hi.y + bi.w);
            *(float4*)&sm[SM_H + (warp + 32 * ii) * HS + lane * 4] = w;
        }
    }
    __syncthreads();

    // ================= Layers =========================================================
    for (int li = 0; li < 2; li++) {
        // --- xl = h @ Wl + bl ; xr = h @ Wr + br. Double-buffered B tiles,
        //     one barrier per k-tile, float2 A broadcasts, FFMA2 accumulate. ---
        for (int which = 0; which < 2; which++) {
            const float* W  = (which == 0 ? lW : rW) + (size_t)li * HID_ * HID_;
            const float* Bv = (which == 0 ? lb : rb) + li * HID_;
            const int dsto  = (which == 0) ? SM_XL : SM_XR;
            #pragma unroll
            for (int ii = 0; ii < 4; ii++) { acc2[ii][0] = 0ull; acc2[ii][1] = 0ull; }
            #pragma unroll
            for (int r = 0; r < 2; r++) {
                int i = tid + THREADS * r;
                int kk = i >> 7, c = i & 127;
                pB[r] = W[kk * HID_ + c];
            }
            for (int t = 0; t < 8; t++) {
                const int k0 = t * 16;
                const int bb = (t & 1) ? SM_AS : SM_BS;
                #pragma unroll
                for (int r = 0; r < 2; r++) {
                    int i = tid + THREADS * r;
                    int kk = i >> 7, c = i & 127;
                    sm[bb + kk * TS + c] = pB[r];
                }
                __syncthreads();
                if (t < 7) {
                    #pragma unroll
                    for (int r = 0; r < 2; r++) {
                        int i = tid + THREADS * r;
                        int kk = i >> 7, c = i & 127;
                        pB[r] = W[(k0 + 16 + kk) * HID_ + c];
                    }
                }
                #pragma unroll
                for (int kk = 0; kk < 16; kk += 2) {
                    float2 a2[4];
                    #pragma unroll
                    for (int ii = 0; ii < 4; ii++)
                        a2[ii] = *(const float2*)&sm[SM_H + (warp + 32 * ii) * HS + k0 + kk];
                    {
                        ulonglong2 bv = *(const ulonglong2*)&sm[bb + kk * TS + lane * 4];
                        #pragma unroll
                        for (int ii = 0; ii < 4; ii++) {
                            unsigned long long ad = dup2(a2[ii].x);
                            ffma2(acc2[ii][0], ad, bv.x);
                            ffma2(acc2[ii][1], ad, bv.y);
                        }
                    }
                    {
                        ulonglong2 bv = *(const ulonglong2*)&sm[bb + (kk + 1) * TS + lane * 4];
                        #pragma unroll
                        for (int ii = 0; ii < 4; ii++) {
                            unsigned long long ad = dup2(a2[ii].y);
                            ffma2(acc2[ii][0], ad, bv.x);
                            ffma2(acc2[ii][1], ad, bv.y);
                        }
                    }
                }
            }
            {
                float4 bi = *(const float4*)&Bv[lane * 4];
                #pragma unroll
                for (int ii = 0; ii < 4; ii++) {
                    float2 lo = unpack2(acc2[ii][0]), hi = unpack2(acc2[ii][1]);
                    float4 w = make_float4(lo.x + bi.x, lo.y + bi.y, hi.x + bi.z, hi.y + bi.w);
                    *(float4*)&sm[dsto + (warp + 32 * ii) * HS + lane * 4] = w;
                }
            }
            __syncthreads();
        }

        // --- fused edge phase (all 4 heads at once) + LayerNorm.
        //     Warp owns nodes {warp, warp+32, +64, +96}; no __syncthreads needed.
        {
            const float4 a4 = *(const float4*)&s_att[li * 128 + lane * 4];

            for (int n = warp; n < C_; n += 32) {
                const int beg = s_rowptr[n], end = s_rowptr[n + 1];
                const int deg = end - beg;
                int sreg[4];
                #pragma unroll
                for (int ch = 0; ch < 4; ch++) {
                    int t = beg + ch * 32 + lane;
                    sreg[ch] = (t < end) ? (int)s_srcs[t] : 0;
                }
                const float4 xr4 = *(const float4*)&sm[SM_XR + n * HS + lane * 4];

                float4 av = make_float4(0.f, 0.f, 0.f, 0.f);
                float psum = 0.0f;

                #pragma unroll
                for (int ch = 0; ch < 4; ch++) {
                    int base = ch * 32;
                    if (base >= deg) break;
                    int lim = min(32, deg - base);
                    #pragma unroll 8
                    for (int j = 0; j < lim; j++) {
                        int s = __shfl_sync(0xFFFFFFFFu, sreg[ch], j);
                        float4 xlv = *(const float4*)&sm[SM_XL + s * HS + lane * 4];
                        float vx = xlv.x + xr4.x; vx = fmaxf(vx, 0.2f * vx);
                        float vy = xlv.y + xr4.y; vy = fmaxf(vy, 0.2f * vy);
                        float vz = xlv.z + xr4.z; vz = fmaxf(vz, 0.2f * vz);
                        float vw = xlv.w + xr4.w; vw = fmaxf(vw, 0.2f * vw);
                        float t = vx * a4.x + vy * a4.y + vz * a4.z + vw * a4.w;
                        // segmented sum over the 8 lanes of this head
                        t += __shfl_xor_sync(0xFFFFFFFFu, t, 4);
                        t += __shfl_xor_sync(0xFFFFFFFFu, t, 2);
                        t += __shfl_xor_sync(0xFFFFFFFFu, t, 1);
                        float p = __expf(t);       // p of this lane's head
                        psum += p;
                        av.x += p * xlv.x; av.y += p * xlv.y;
                        av.z += p * xlv.z; av.w += p * xlv.w;
                    }
                }
                const float inv = 1.0f / (psum + 1e-16f);
                av.x *= inv; av.y *= inv; av.z *= inv; av.w *= inv;
                *(float4*)&sm[SM_XR + n * HS + lane * 4] = av;   // gat out for node n

                if (li == 1) {
                    // recompute p per edge; attn map gets mean over heads of alpha
                    float aacc[4] = {0.f, 0.f, 0.f, 0.f};
                    #pragma unroll
                    for (int ch = 0; ch < 4; ch++) {
                        int base = ch * 32;
                        if (base >= deg) break;
                        int lim = min(32, deg - base);
                        #pragma unroll 8
                        for (int j = 0; j < lim; j++) {
                            int s = __shfl_sync(0xFFFFFFFFu, sreg[ch], j);
                            float4 xlv = *(const float4*)&sm[SM_XL + s * HS + lane * 4];
                            float vx = xlv.x + xr4.x; vx = fmaxf(vx, 0.2f * vx);
                            float vy = xlv.y + xr4.y; vy = fmaxf(vy, 0.2f * vy);
                            float vz = xlv.z + xr4.z; vz = fmaxf(vz, 0.2f * vz);
                            float vw = xlv.w + xr4.w; vw = fmaxf(vw, 0.2f * vw);
                            float t = vx * a4.x + vy * a4.y + vz * a4.z + vw * a4.w;
                            t += __shfl_xor_sync(0xFFFFFFFFu, t, 4);
                            t += __shfl_xor_sync(0xFFFFFFFFu, t, 2);
                            t += __shfl_xor_sync(0xFFFFFFFFu, t, 1);
                            float pin = __expf(t) * inv;
                            // sum across the 4 heads (groups of 8)
                            pin += __shfl_xor_sync(0xFFFFFFFFu, pin, 8);
                            pin += __shfl_xor_sync(0xFFFFFFFFu, pin, 16);
                            if (lane == j) aacc[ch] = pin;
                        }
                    }
                    #pragma unroll
                    for (int ch = 0; ch < 4; ch++) {
                        int t = beg + ch * 32 + lane;
                        if (t < end) atomicAdd(&myattn[n * C_ + sreg[ch]], aacc[ch] * 0.25f);
                    }
                }

                // --- bias + ELU + residual + LayerNorm for node n (same warp) ---
                {
                    const float4 gb4 = *(const float4*)&gbias[li * HID_ + lane * 4];
                    float4 h4 = *(const float4*)&sm[SM_H + n * HS + lane * 4];
                    float v0 = av.x + gb4.x, v1 = av.y + gb4.y, v2 = av.z + gb4.z, v3 = av.w + gb4.w;
                    v0 = v0 > 0.f ? v0 : expm1f(v0);
                    v1 = v1 > 0.f ? v1 : expm1f(v1);
                    v2 = v2 > 0.f ? v2 : expm1f(v2);
                    v3 = v3 > 0.f ? v3 : expm1f(v3);
                    v0 += h4.x; v1 += h4.y; v2 += h4.z; v3 += h4.w;
                    float mu = warpSum(v0 + v1 + v2 + v3) * (1.0f / 128.0f);
                    float d0 = v0 - mu, d1 = v1 - mu, d2 = v2 - mu, d3 = v3 - mu;
                    float var = warpSum(d0 * d0 + d1 * d1 + d2 * d2 + d3 * d3) * (1.0f / 128.0f);
                    float rstd = rsqrtf(var + 1e-5f);
                    const float4 g4 = *(const float4*)&lng[li * HID_ + lane * 4];
                    const float4 b4 = *(const float4*)&lnb[li * HID_ + lane * 4];
                    float4 o;
                    o.x = d0 * rstd * g4.x + b4.x;
                    o.y = d1 * rstd * g4.y + b4.y;
                    o.z = d2 * rstd * g4.z + b4.z;
                    o.w = d3 * rstd * g4.w + b4.w;
                    *(float4*)&sm[SM_H + n * HS + lane * 4] = o;
                }
            }
        }
        __syncthreads();
    }

    // ================= Projection: out[b,l,c] = h[c,:] . pW[:,l] + pb[l] ==============
    for (int half = 0; half < 2; half++) {
        #pragma unroll
        for (int ii = 0; ii < 4; ii++) { acc2[ii][0] = 0ull; acc2[ii][1] = 0ull; }
        #pragma unroll
        for (int r = 0; r < 2; r++) {
            int i = tid + THREADS * r;
            int kk = i >> 7, c = i & 127;
            pB[r] = pW[kk * L_ + half * 128 + c];
        }
        for (int t = 0; t < 8; t++) {
            const int k0 = t * 16;
            const int bb = (t & 1) ? SM_AS : SM_BS;
            #pragma unroll
            for (int r = 0; r < 2; r++) {
                int i = tid + THREADS * r;
                int kk = i >> 7, c = i & 127;
                sm[bb + kk * TS + c] = pB[r];
            }
            __syncthreads();
            if (t < 7) {
                #pragma unroll
                for (int r = 0; r < 2; r++) {
                    int i = tid + THREADS * r;
                    int kk = i >> 7, c = i & 127;
                    pB[r] = pW[(k0 + 16 + kk) * L_ + half * 128 + c];
                }
            }
            #pragma unroll
            for (int kk = 0; kk < 16; kk += 2) {
                float2 a2[4];
                #pragma unroll
                for (int ii = 0; ii < 4; ii++)
                    a2[ii] = *(const float2*)&sm[SM_H + (warp + 32 * ii) * HS + k0 + kk];
                {
                    ulonglong2 bv = *(const ulonglong2*)&sm[bb + kk * TS + lane * 4];
                    #pragma unroll
                    for (int ii = 0; ii < 4; ii++) {
                        unsigned long long ad = dup2(a2[ii].x);
                        ffma2(acc2[ii][0], ad, bv.x);
                        ffma2(acc2[ii][1], ad, bv.y);
                    }
                }
                {
                    ulonglong2 bv = *(const ulonglong2*)&sm[bb + (kk + 1) * TS + lane * 4];
                    #pragma unroll
                    for (int ii = 0; ii < 4; ii++) {
                        unsigned long long ad = dup2(a2[ii].y);
                        ffma2(acc2[ii][0], ad, bv.x);
                        ffma2(acc2[ii][1], ad, bv.y);
                    }
                }
            }
        }
        // stage as T[c][l_local] (float4, conflict-free stores), then coalesced write
        {
            float4 bi = *(const float4*)&pb[half * 128 + lane * 4];
            #pragma unroll
            for (int ii = 0; ii < 4; ii++) {
                float2 lo = unpack2(acc2[ii][0]), hi = unpack2(acc2[ii][1]);
                float4 w = make_float4(lo.x + bi.x, lo.y + bi.y, hi.x + bi.z, hi.y + bi.w);
                *(float4*)&sm[SM_XL + (warp + 32 * ii) * HS + lane * 4] = w;
            }
        }
        __syncthreads();
        for (int idx = tid; idx < 128 * C_; idx += THREADS) {
            int ll = idx >> 7, c = idx & 127;
            out[(size_t)b * L_ * C_ + (half * 128 + ll) * C_ + c] = sm[SM_XL + c * HS + ll];
        }
        __syncthreads();
    }
}

// ---------------------------------------------------------------------------
extern "C" void kernel_launch(void* const* d_in, const int* in_sizes, int n_in,
                              void* d_out, int out_size)
{
    const float* x    = (const float*)d_in[0];
    const int*   ei   = (const int*)  d_in[1];   // int32 or int64 (auto-detected)
    const float* embW = (const float*)d_in[2];
    const float* embB = (const float*)d_in[3];
    const float* lW   = (const float*)d_in[4];
    const float* lb   = (const float*)d_in[5];
    const float* rW   = (const float*)d_in[6];
    const float* rb   = (const float*)d_in[7];
    const float* att  = (const float*)d_in[8];
    const float* gb   = (const float*)d_in[9];
    const float* lng  = (const float*)d_in[10];
    const float* lnb  = (const float*)d_in[11];
    const float* pW   = (const float*)d_in[12];
    const float* pb   = (const float*)d_in[13];

    cudaFuncSetAttribute(gat_main_kernel,
                         cudaFuncAttributeMaxDynamicSharedMemorySize, SMEM_BYTES);

    prep_kernel<<<1, 256>>>(ei);
    gat_main_kernel<<<B_, THREADS, SMEM_BYTES>>>(x, embW, embB, lW, lb, rW, rb,
                                                 att, gb, lng, lnb, pW, pb,
                                                 (float*)d_out);
}